// round 16
// baseline (speedup 1.0000x reference)
#include <cuda_runtime.h>
#include <cuda_bf16.h>
#include <cstdint>
#include <math.h>

typedef unsigned int u32;
typedef __nv_bfloat16 bf16;

// Problem constants
#define BB   2
#define NN   2048
#define DIMM 1024
#define HH   16
#define DHH  64
#define MM   (BB*NN)          // 4096 tokens

// Scratch (allocation-free rule: __device__ globals)
__device__ bf16  g_yh [MM * DIMM];
__device__ bf16  g_yl [MM * DIMM];
__device__ bf16  g_qkvh[MM * 3 * DIMM];
__device__ bf16  g_qkvl[MM * 3 * DIMM];
__device__ bf16  g_oh [MM * DIMM];
__device__ bf16  g_ol [MM * DIMM];
__device__ bf16  g_cawh[DIMM * 3 * DIMM];
__device__ bf16  g_cawl[DIMM * 3 * DIMM];
__device__ bf16  g_cpwh[DIMM * DIMM];
__device__ bf16  g_cpwl[DIMM * DIMM];
__device__ bf16  g_towh[DIMM * DIMM];
__device__ bf16  g_towl[DIMM * DIMM];
__device__ bf16  g_w2h [DIMM * DIMM];     // W2 = cpw @ tow^T
__device__ bf16  g_w2l [DIMM * DIMM];
__device__ float g_b2  [DIMM];            // b2 = cpb @ tow^T
__device__ float g_wpart[8 * DIMM * DIMM];// split-K partials for W2

__device__ __forceinline__ float warp_sum(float v) {
#pragma unroll
    for (int o = 16; o; o >>= 1) v += __shfl_xor_sync(0xffffffffu, v, o);
    return v;
}

// ---------------------------------------------------------------------------
// MMA / ldmatrix / cp.async / split helpers
// ---------------------------------------------------------------------------
__device__ __forceinline__ void ldm4(u32* r, const bf16* p) {
    u32 a = (u32)__cvta_generic_to_shared(p);
    asm volatile("ldmatrix.sync.aligned.m8n8.x4.shared.b16 {%0,%1,%2,%3}, [%4];"
        : "=r"(r[0]), "=r"(r[1]), "=r"(r[2]), "=r"(r[3]) : "r"(a));
}
__device__ __forceinline__ void ldm4t(u32* r, const bf16* p) {
    u32 a = (u32)__cvta_generic_to_shared(p);
    asm volatile("ldmatrix.sync.aligned.m8n8.x4.trans.shared.b16 {%0,%1,%2,%3}, [%4];"
        : "=r"(r[0]), "=r"(r[1]), "=r"(r[2]), "=r"(r[3]) : "r"(a));
}
__device__ __forceinline__ void mma16816(float* c, const u32* a, const u32* b) {
    asm volatile("mma.sync.aligned.m16n8k16.row.col.f32.bf16.bf16.f32 "
        "{%0,%1,%2,%3}, {%4,%5,%6,%7}, {%8,%9}, {%0,%1,%2,%3};"
        : "+f"(c[0]), "+f"(c[1]), "+f"(c[2]), "+f"(c[3])
        : "r"(a[0]), "r"(a[1]), "r"(a[2]), "r"(a[3]), "r"(b[0]), "r"(b[1]));
}
__device__ __forceinline__ void cpa16(bf16* dst, const bf16* src) {
    u32 d = (u32)__cvta_generic_to_shared(dst);
    asm volatile("cp.async.cg.shared.global [%0], [%1], 16;" :: "r"(d), "l"(src));
}
__device__ __forceinline__ void cpa_commit() {
    asm volatile("cp.async.commit_group;");
}
__device__ __forceinline__ void cpa_wait0() {
    asm volatile("cp.async.wait_group 0;");
}
__device__ __forceinline__ void cpa_wait1() {
    asm volatile("cp.async.wait_group 1;");
}
__device__ __forceinline__ u32 p2(float a, float b) {
    __nv_bfloat162 t = __floats2bfloat162_rn(a, b);
    return *reinterpret_cast<u32*>(&t);
}
__device__ __forceinline__ void split2(float a, float b, u32& hi, u32& lo) {
    float ha = __bfloat162float(__float2bfloat16_rn(a));
    float hb = __bfloat162float(__float2bfloat16_rn(b));
    hi = p2(a, b);
    lo = p2(a - ha, b - hb);
}
__device__ __forceinline__ void split_store4(float4 v, bf16* ph, bf16* pl) {
    float hx = __bfloat162float(__float2bfloat16_rn(v.x));
    float hy = __bfloat162float(__float2bfloat16_rn(v.y));
    float hz = __bfloat162float(__float2bfloat16_rn(v.z));
    float hw = __bfloat162float(__float2bfloat16_rn(v.w));
    *reinterpret_cast<uint2*>(ph) = make_uint2(p2(hx, hy), p2(hz, hw));
    *reinterpret_cast<uint2*>(pl) =
        make_uint2(p2(v.x - hx, v.y - hy), p2(v.z - hz, v.w - hw));
}

// ---------------------------------------------------------------------------
// fp32 -> bf16 hi/lo split of all three weights in one launch
// ---------------------------------------------------------------------------
__global__ void __launch_bounds__(256) split_all_kernel(
        const float* __restrict__ caw, bf16* __restrict__ cawh, bf16* __restrict__ cawl,
        const float* __restrict__ cpw, bf16* __restrict__ cpwh, bf16* __restrict__ cpwl,
        const float* __restrict__ tow, bf16* __restrict__ towh, bf16* __restrict__ towl) {
    int bid = blockIdx.x;
    const float* in;
    bf16 *h, *l;
    int base;
    if (bid < 3072)      { in = caw; h = cawh; l = cawl; base = bid; }
    else if (bid < 4096) { in = cpw; h = cpwh; l = cpwl; base = bid - 3072; }
    else                 { in = tow; h = towh; l = towl; base = bid - 4096; }
    int i = (base * 256 + threadIdx.x) * 4;
    float4 v = *(const float4*)(in + i);
    split_store4(v, h + i, l + i);
}

// ---------------------------------------------------------------------------
// reduce 8 split-K partials -> bf16 hi/lo
// ---------------------------------------------------------------------------
__global__ void __launch_bounds__(256) wreduce_kernel(const float* __restrict__ part,
                                                      bf16* __restrict__ h,
                                                      bf16* __restrict__ l) {
    int i = (blockIdx.x * 256 + threadIdx.x) * 4;
    float4 s = *(const float4*)(part + i);
#pragma unroll
    for (int z = 1; z < 8; z++) {
        float4 v = *(const float4*)(part + (size_t)z * DIMM * DIMM + i);
        s.x += v.x; s.y += v.y; s.z += v.z; s.w += v.w;
    }
    split_store4(s, h + i, l + i);
}

// ---------------------------------------------------------------------------
// b2[j] = sum_k cpb[k] * tow[j,k]. One warp per output row.
// ---------------------------------------------------------------------------
__global__ void __launch_bounds__(256) bias_fold_kernel(
        const float* __restrict__ cpb, const float* __restrict__ tow,
        float* __restrict__ b2) {
    int j = blockIdx.x * 8 + (threadIdx.x >> 5);
    int lane = threadIdx.x & 31;
    const float* tr = tow + (size_t)j * DIMM;
    float s = 0.f;
#pragma unroll
    for (int k = lane * 4; k < DIMM; k += 128) {
        float4 t = *(const float4*)(tr + k);
        float4 c = *(const float4*)(cpb + k);
        s += t.x * c.x + t.y * c.y + t.z * c.z + t.w * c.w;
    }
    s = warp_sum(s);
    if (lane == 0) b2[j] = s;
}

// ---------------------------------------------------------------------------
// LayerNorm -> bf16 hi/lo
// ---------------------------------------------------------------------------
__global__ void __launch_bounds__(256) ln_kernel(const float* __restrict__ x,
                                                 const float* __restrict__ g,
                                                 const float* __restrict__ b,
                                                 bf16* __restrict__ yh,
                                                 bf16* __restrict__ yl) {
    int row = blockIdx.x;
    int t = threadIdx.x;
    const float* xr = x + (size_t)row * DIMM;
    float4 v = *(const float4*)(xr + t * 4);
    float s  = v.x + v.y + v.z + v.w;
    float ss = v.x*v.x + v.y*v.y + v.z*v.z + v.w*v.w;
    __shared__ float red[16];
    float s1 = warp_sum(s), s2 = warp_sum(ss);
    int w = t >> 5, lane = t & 31;
    if (lane == 0) { red[w] = s1; red[8 + w] = s2; }
    __syncthreads();
    float tot = 0.f, tot2 = 0.f;
#pragma unroll
    for (int i = 0; i < 8; i++) { tot += red[i]; tot2 += red[8 + i]; }
    float mu  = tot  * (1.f / DIMM);
    float var = tot2 * (1.f / DIMM) - mu * mu;
    float inv = rsqrtf(var + 1e-5f);
    float4 gv = *(const float4*)(g + t * 4);
    float4 bv = *(const float4*)(b + t * 4);
    float4 o;
    o.x = (v.x - mu) * inv * gv.x + bv.x;
    o.y = (v.y - mu) * inv * gv.y + bv.y;
    o.z = (v.z - mu) * inv * gv.z + bv.z;
    o.w = (v.w - mu) * inv * gv.w + bv.w;
    size_t off = (size_t)row * DIMM + t * 4;
    split_store4(o, yh + off, yl + off);
}

// ---------------------------------------------------------------------------
// bf16x3 tensor-core GEMM, 128x256 tile, BK=32, 2-stage cp.async. (R11)
// OMODE: 0 fp32 out, 1 bf16 hi/lo out, 2 qkv fused (bias+L2 norm+split),
//        3 split-K partial fp32 out
// ---------------------------------------------------------------------------
#define SA3 40
#define SB3 264

template <bool TRANSB, bool HASBIAS, int OMODE>
__global__ void __launch_bounds__(256) hgemm3_kernel(
        const bf16* __restrict__ Ahg, const bf16* __restrict__ Alg,
        const bf16* __restrict__ Bhg, const bf16* __restrict__ Blg,
        const float* __restrict__ bias,
        float* __restrict__ C, bf16* __restrict__ Ch, bf16* __restrict__ Cl,
        int M, int N, int K) {
    extern __shared__ __align__(16) bf16 smem[];
    constexpr int A_E = 128 * SA3;
    constexpr int B_E = TRANSB ? 256 * SA3 : 32 * SB3;
    constexpr int STAGE_E = 2 * A_E + 2 * B_E;

    int tid = threadIdx.x;
    int bm = blockIdx.y * 128, bn = blockIdx.x * 256;
    int wid = tid >> 5, lane = tid & 31;
    int wm = (wid & 3) * 32, wn = (wid >> 2) * 128;
    int grp = lane >> 3, lr = lane & 7;

    if (OMODE == 3) C += (size_t)blockIdx.z * M * N;

    auto load_stage = [&](int s, int k0) {
        bf16* sAh = smem + s * STAGE_E;
        bf16* sAl = sAh + A_E;
        bf16* sBh = sAl + A_E;
        bf16* sBl = sBh + B_E;
#pragma unroll
        for (int i = 0; i < 2; i++) {
            int c = tid + i * 256;
            int row = c >> 2, kg = (c & 3) * 8;
            size_t src = (size_t)(bm + row) * K + k0 + kg;
            cpa16(&sAh[row * SA3 + kg], Ahg + src);
            cpa16(&sAl[row * SA3 + kg], Alg + src);
        }
        if (!TRANSB) {
#pragma unroll
            for (int i = 0; i < 4; i++) {
                int c = tid + i * 256;
                int row = c >> 5, col = (c & 31) * 8;
                size_t src = (size_t)(k0 + row) * N + bn + col;
                cpa16(&sBh[row * SB3 + col], Bhg + src);
                cpa16(&sBl[row * SB3 + col], Blg + src);
            }
        } else {
#pragma unroll
            for (int i = 0; i < 4; i++) {
                int c = tid + i * 256;
                int row = c >> 2, kg = (c & 3) * 8;
                size_t src = (size_t)(bn + row) * K + k0 + kg;
                cpa16(&sBh[row * SA3 + kg], Bhg + src);
                cpa16(&sBl[row * SA3 + kg], Blg + src);
            }
        }
    };

    float acc[2][16][4];
#pragma unroll
    for (int i = 0; i < 2; i++)
#pragma unroll
        for (int j = 0; j < 16; j++)
#pragma unroll
            for (int q = 0; q < 4; q++) acc[i][j][q] = 0.f;

    int arow0 = wm + ((grp & 1) << 3) + lr;

    int NK_total = K / 32;
    int it0 = 0, it1 = NK_total;
    if (OMODE == 3) {
        int per = NK_total / gridDim.z;
        it0 = blockIdx.z * per;
        it1 = it0 + per;
    }

    load_stage(0, it0 * 32);
    cpa_commit();

    int stage = 0;
    for (int it = it0; it < it1; it++) {
        cpa_wait0();
        __syncthreads();
        if (it + 1 < it1) { load_stage(stage ^ 1, (it + 1) * 32); cpa_commit(); }

        bf16* sAh = smem + stage * STAGE_E;
        bf16* sAl = sAh + A_E;
        bf16* sBh = sAl + A_E;
        bf16* sBl = sBh + B_E;

#pragma unroll
        for (int ks = 0; ks < 2; ks++) {
            int acol = ks * 16 + ((grp & 2) ? 8 : 0);
            u32 ah[2][4], al[2][4];
            ldm4(ah[0], &sAh[arow0 * SA3 + acol]);
            ldm4(ah[1], &sAh[(arow0 + 16) * SA3 + acol]);
            ldm4(al[0], &sAl[arow0 * SA3 + acol]);
            ldm4(al[1], &sAl[(arow0 + 16) * SA3 + acol]);

#pragma unroll
            for (int nb = 0; nb < 8; nb++) {
                u32 rh[4], rl[4];
                if (!TRANSB) {
                    int krow = ks * 16 + ((grp & 1) << 3) + lr;
                    int ncol = wn + nb * 16 + ((grp & 2) ? 8 : 0);
                    ldm4t(rh, &sBh[krow * SB3 + ncol]);
                    ldm4t(rl, &sBl[krow * SB3 + ncol]);
                } else {
                    int nrow = wn + nb * 16 + ((grp & 2) ? 8 : 0) + lr;
                    int kcol = ks * 16 + ((grp & 1) ? 8 : 0);
                    ldm4(rh, &sBh[nrow * SA3 + kcol]);
                    ldm4(rl, &sBl[nrow * SA3 + kcol]);
                }
                int nf0 = 2 * nb, nf1 = 2 * nb + 1;
#pragma unroll
                for (int mi = 0; mi < 2; mi++) {
                    mma16816(acc[mi][nf0], ah[mi], rh);
                    mma16816(acc[mi][nf0], al[mi], rh);
                    mma16816(acc[mi][nf0], ah[mi], rl);
                    mma16816(acc[mi][nf1], ah[mi], rh + 2);
                    mma16816(acc[mi][nf1], al[mi], rh + 2);
                    mma16816(acc[mi][nf1], ah[mi], rl + 2);
                }
            }
        }
        __syncthreads();
        stage ^= 1;
    }

    int r = lane >> 2, c2v = (lane & 3) * 2;

    if (OMODE == 2) {
        bool donorm = (bn < 2 * DIMM);
#pragma unroll
        for (int nf = 0; nf < 16; nf++) {
            int col = bn + wn + nf * 8 + c2v;
            float b0 = bias[col], b1 = bias[col + 1];
#pragma unroll
            for (int mi = 0; mi < 2; mi++) {
                acc[mi][nf][0] += b0; acc[mi][nf][1] += b1;
                acc[mi][nf][2] += b0; acc[mi][nf][3] += b1;
            }
        }
#pragma unroll
        for (int gh = 0; gh < 2; gh++) {
            float ss[2][2] = {{0.f, 0.f}, {0.f, 0.f}};
#pragma unroll
            for (int nf = gh * 8; nf < gh * 8 + 8; nf++)
#pragma unroll
                for (int mi = 0; mi < 2; mi++) {
                    ss[mi][0] += acc[mi][nf][0] * acc[mi][nf][0]
                               + acc[mi][nf][1] * acc[mi][nf][1];
                    ss[mi][1] += acc[mi][nf][2] * acc[mi][nf][2]
                               + acc[mi][nf][3] * acc[mi][nf][3];
                }
            float inv[2][2];
#pragma unroll
            for (int mi = 0; mi < 2; mi++)
#pragma unroll
                for (int hf = 0; hf < 2; hf++) {
                    float v = ss[mi][hf];
                    v += __shfl_xor_sync(0xffffffffu, v, 1);
                    v += __shfl_xor_sync(0xffffffffu, v, 2);
                    inv[mi][hf] = donorm ? 1.f / fmaxf(sqrtf(v), 1e-12f) : 1.f;
                }
#pragma unroll
            for (int nf = gh * 8; nf < gh * 8 + 8; nf++) {
                int col = bn + wn + nf * 8 + c2v;
#pragma unroll
                for (int mi = 0; mi < 2; mi++) {
                    int row0 = bm + wm + mi * 16 + r;
                    size_t o0 = (size_t)row0 * N + col;
                    size_t o1 = (size_t)(row0 + 8) * N + col;
                    u32 hi, lo;
                    split2(acc[mi][nf][0] * inv[mi][0],
                           acc[mi][nf][1] * inv[mi][0], hi, lo);
                    *(u32*)(Ch + o0) = hi; *(u32*)(Cl + o0) = lo;
                    split2(acc[mi][nf][2] * inv[mi][1],
                           acc[mi][nf][3] * inv[mi][1], hi, lo);
                    *(u32*)(Ch + o1) = hi; *(u32*)(Cl + o1) = lo;
                }
            }
        }
        return;
    }

#pragma unroll
    for (int nf = 0; nf < 16; nf++) {
        int col = bn + wn + nf * 8 + c2v;
        float b0v = 0.f, b1v = 0.f;
        if (HASBIAS) { b0v = bias[col]; b1v = bias[col + 1]; }
#pragma unroll
        for (int mi = 0; mi < 2; mi++) {
            int row0 = bm + wm + mi * 16 + r;
            float v00 = acc[mi][nf][0] + b0v, v01 = acc[mi][nf][1] + b1v;
            float v10 = acc[mi][nf][2] + b0v, v11 = acc[mi][nf][3] + b1v;
            size_t o0 = (size_t)row0 * N + col;
            size_t o1 = (size_t)(row0 + 8) * N + col;
            if (OMODE == 1) {
                u32 hi, lo;
                split2(v00, v01, hi, lo);
                *(u32*)(Ch + o0) = hi; *(u32*)(Cl + o0) = lo;
                split2(v10, v11, hi, lo);
                *(u32*)(Ch + o1) = hi; *(u32*)(Cl + o1) = lo;
            } else {
                *(float2*)(C + o0) = make_float2(v00, v01);
                *(float2*)(C + o1) = make_float2(v10, v11);
            }
        }
    }
}

// ---------------------------------------------------------------------------
// Tensor-core causal flash-attention (bf16x3, fp32 softmax). R13 math,
// __launch_bounds__(256, 2): cap regs at 128 so 2 CTAs co-reside per SM
// (2 x 73.7KB smem fits in 228KB) -> 4 warps/SMSP to hide the serial
// softmax phase with the co-resident CTA's MMAs.
// ---------------------------------------------------------------------------
#define KST 72
#define TILE_E (64 * KST)
#define ATT_SMEM (2 * 4 * TILE_E * 2)

__global__ void __launch_bounds__(256, 2) attn_mma_kernel(
        const bf16* __restrict__ qkvh,
        const bf16* __restrict__ qkvl,
        bf16* __restrict__ oh, bf16* __restrict__ ol) {
    extern __shared__ __align__(16) bf16 asmem[];

    int bh_ = blockIdx.y;
    int b = bh_ >> 4, h = bh_ & 15;
    int q0 = (gridDim.x - 1 - blockIdx.x) * 128;
    int tid = threadIdx.x, wid = tid >> 5, lane = tid & 31;
    int grp = lane >> 3, lr = lane & 7;
    int wm = wid * 16;

    const size_t rs = 3 * DIMM;
    const bf16* qh_base = qkvh + (size_t)b * NN * rs + h * DHH;
    const bf16* ql_base = qkvl + (size_t)b * NN * rs + h * DHH;
    const bf16* kh_base = qh_base + DIMM;
    const bf16* kl_base = ql_base + DIMM;
    const bf16* vh_base = qh_base + 2 * DIMM;
    const bf16* vl_base = ql_base + 2 * DIMM;

    auto load_kv = [&](int s, int j0) {
        bf16* kh = asmem + s * 4 * TILE_E;
        bf16* kl = kh + TILE_E;
        bf16* vh = kh + 2 * TILE_E;
        bf16* vl = kh + 3 * TILE_E;
#pragma unroll
        for (int i = 0; i < 2; i++) {
            int c = tid + i * 256;
            int r = c >> 3, cc = (c & 7) * 8;
            size_t off = (size_t)(j0 + r) * rs + cc;
            cpa16(&kh[r * KST + cc], kh_base + off);
            cpa16(&kl[r * KST + cc], kl_base + off);
            cpa16(&vh[r * KST + cc], vh_base + off);
            cpa16(&vl[r * KST + cc], vl_base + off);
        }
    };

    load_kv(0, 0);
    cpa_commit();

    {
        bf16* q_h0 = asmem + 4 * TILE_E;
        bf16* q_l0 = q_h0 + TILE_E;
        bf16* q_h1 = q_h0 + 2 * TILE_E;
        bf16* q_l1 = q_h0 + 3 * TILE_E;
        for (int i = tid; i < 128 * 8; i += 256) {
            int r = i >> 3, c = (i & 7) * 8;
            size_t off = (size_t)(q0 + r) * rs + c;
            bf16* dh = (r < 64) ? &q_h0[r * KST + c] : &q_h1[(r - 64) * KST + c];
            bf16* dl = (r < 64) ? &q_l0[r * KST + c] : &q_l1[(r - 64) * KST + c];
            *(uint4*)dh = *(const uint4*)(qh_base + off);
            *(uint4*)dl = *(const uint4*)(ql_base + off);
        }
    }
    __syncthreads();
    u32 aq_h[4][4], aq_l[4][4];
    {
        bf16* q_h0 = asmem + 4 * TILE_E;
        const bf16* bh_p = (wm < 64) ? q_h0 : q_h0 + 2 * TILE_E;
        const bf16* bl_p = (wm < 64) ? q_h0 + TILE_E : q_h0 + 3 * TILE_E;
        int arow = (wm & 63) + ((grp & 1) << 3) + lr;
#pragma unroll
        for (int ks = 0; ks < 4; ks++) {
            int acol = ks * 16 + ((grp & 2) ? 8 : 0);
            ldm4(aq_h[ks], &bh_p[arow * KST + acol]);
            ldm4(aq_l[ks], &bl_p[arow * KST + acol]);
        }
    }
    __syncthreads();

    float m0 = -1e30f, m1 = -1e30f, l0 = 0.f, l1 = 0.f;
    float acc[8][4];
#pragma unroll
    for (int i = 0; i < 8; i++)
#pragma unroll
        for (int j = 0; j < 4; j++) acc[i][j] = 0.f;

    int c2 = (lane & 3) * 2;
    int qrow0 = q0 + wm + (lane >> 2);
    int qrow1 = qrow0 + 8;
    int ntiles = q0 / 64 + 2;

    for (int t = 0; t < ntiles; t++) {
        int s = t & 1;
        int j0 = t * 64;
        if (t + 1 < ntiles) {
            load_kv(s ^ 1, (t + 1) * 64);
            cpa_commit();
            cpa_wait1();
        } else {
            cpa_wait0();
        }
        __syncthreads();

        bf16* skh = asmem + s * 4 * TILE_E;
        bf16* skl = skh + TILE_E;
        bf16* svh = skh + 2 * TILE_E;
        bf16* svl = skh + 3 * TILE_E;

        float sv[8][4];
#pragma unroll
        for (int i = 0; i < 8; i++)
#pragma unroll
            for (int j = 0; j < 4; j++) sv[i][j] = 0.f;

#pragma unroll
        for (int ks = 0; ks < 4; ks++) {
            int kcol = ks * 16 + ((grp & 1) ? 8 : 0);
            u32 kh[4][4], kl[4][4];
#pragma unroll
            for (int nb = 0; nb < 4; nb++) {
                int nrow = nb * 16 + ((grp & 2) ? 8 : 0) + lr;
                ldm4(kh[nb], &skh[nrow * KST + kcol]);
                ldm4(kl[nb], &skl[nrow * KST + kcol]);
            }
            // term-major: 8 distinct accumulators between same-acc MMAs
#pragma unroll
            for (int nb = 0; nb < 4; nb++) {
                mma16816(sv[2 * nb],     aq_h[ks], &kh[nb][0]);
                mma16816(sv[2 * nb + 1], aq_h[ks], &kh[nb][2]);
            }
#pragma unroll
            for (int nb = 0; nb < 4; nb++) {
                mma16816(sv[2 * nb],     aq_l[ks], &kh[nb][0]);
                mma16816(sv[2 * nb + 1], aq_l[ks], &kh[nb][2]);
            }
#pragma unroll
            for (int nb = 0; nb < 4; nb++) {
                mma16816(sv[2 * nb],     aq_h[ks], &kl[nb][0]);
                mma16816(sv[2 * nb + 1], aq_h[ks], &kl[nb][2]);
            }
        }

        float mx0 = -1e30f, mx1 = -1e30f;
#pragma unroll
        for (int nf = 0; nf < 8; nf++) {
            int key = j0 + nf * 8 + c2;
#pragma unroll
            for (int c = 0; c < 2; c++) {
                float v0 = sv[nf][c] * 8.0f;
                float v1 = sv[nf][2 + c] * 8.0f;
                if (key + c > qrow0) v0 = -1e30f;
                if (key + c > qrow1) v1 = -1e30f;
                sv[nf][c] = v0; sv[nf][2 + c] = v1;
                mx0 = fmaxf(mx0, v0); mx1 = fmaxf(mx1, v1);
            }
        }
        mx0 = fmaxf(mx0, __shfl_xor_sync(0xffffffffu, mx0, 1));
        mx0 = fmaxf(mx0, __shfl_xor_sync(0xffffffffu, mx0, 2));
        mx1 = fmaxf(mx1, __shfl_xor_sync(0xffffffffu, mx1, 1));
        mx1 = fmaxf(mx1, __shfl_xor_sync(0xffffffffu, mx1, 2));
        float nm0 = fmaxf(m0, mx0), nm1 = fmaxf(m1, mx1);
        float al0 = __expf(m0 - nm0), al1 = __expf(m1 - nm1);
        m0 = nm0; m1 = nm1;

        float ls0 = 0.f, ls1 = 0.f;
        u32 ph[4][4], pl[4][4];
#pragma unroll
        for (int j = 0; j < 4; j++) {
            float e0 = __expf(sv[2 * j][0] - m0);
            float e1 = __expf(sv[2 * j][1] - m0);
            float e2 = __expf(sv[2 * j][2] - m1);
            float e3 = __expf(sv[2 * j][3] - m1);
            float e4 = __expf(sv[2 * j + 1][0] - m0);
            float e5 = __expf(sv[2 * j + 1][1] - m0);
            float e6 = __expf(sv[2 * j + 1][2] - m1);
            float e7 = __expf(sv[2 * j + 1][3] - m1);
            ls0 += e0 + e1 + e4 + e5;
            ls1 += e2 + e3 + e6 + e7;
            split2(e0, e1, ph[j][0], pl[j][0]);
            split2(e2, e3, ph[j][1], pl[j][1]);
            split2(e4, e5, ph[j][2], pl[j][2]);
            split2(e6, e7, ph[j][3], pl[j][3]);
        }
        ls0 += __shfl_xor_sync(0xffffffffu, ls0, 1);
        ls0 += __shfl_xor_sync(0xffffffffu, ls0, 2);
        ls1 += __shfl_xor_sync(0xffffffffu, ls1, 1);
        ls1 += __shfl_xor_sync(0xffffffffu, ls1, 2);
        l0 = l0 * al0 + ls0;
        l1 = l1 * al1 + ls1;
#pragma unroll
        for (int nf = 0; nf < 8; nf++) {
            acc[nf][0] *= al0; acc[nf][1] *= al0;
            acc[nf][2] *= al1; acc[nf][3] *= al1;
        }

#pragma unroll
        for (int ks = 0; ks < 4; ks++) {
            int krow = ks * 16 + ((grp & 1) ? 8 : 0) + lr;
            u32 vh[4][4], vl[4][4];
#pragma unroll
            for (int nb = 0; nb < 4; nb++) {
                int ncol = nb * 16 + ((grp & 2) ? 8 : 0);
                ldm4t(vh[nb], &svh[krow * KST + ncol]);
                ldm4t(vl[nb], &svl[krow * KST + ncol]);
            }
            // term-major reorder (see S loop)
#pragma unroll
            for (int nb = 0; nb < 4; nb++) {
                mma16816(acc[2 * nb],     ph[ks], &vh[nb][0]);
                mma16816(acc[2 * nb + 1], ph[ks], &vh[nb][2]);
            }
#pragma unroll
            for (int nb = 0; nb < 4; nb++) {
                mma16816(acc[2 * nb],     pl[ks], &vh[nb][0]);
                mma16816(acc[2 * nb + 1], pl[ks], &vh[nb][2]);
            }
#pragma unroll
            for (int nb = 0; nb < 4; nb++) {
                mma16816(acc[2 * nb],     ph[ks], &vl[nb][0]);
                mma16816(acc[2 * nb + 1], ph[ks], &vl[nb][2]);
            }
        }
        __syncthreads();
    }

    float inv0 = 1.f / l0, inv1 = 1.f / l1;
    size_t o0 = ((size_t)(b * NN) + qrow0) * DIMM + h * DHH;
    size_t o1 = o0 + (size_t)8 * DIMM;
#pragma unroll
    for (int nf = 0; nf < 8; nf++) {
        u32 hi, lo;
        split2(acc[nf][0] * inv0, acc[nf][1] * inv0, hi, lo);
        *(u32*)(oh + o0 + nf * 8 + c2) = hi;
        *(u32*)(ol + o0 + nf * 8 + c2) = lo;
        split2(acc[nf][2] * inv1, acc[nf][3] * inv1, hi, lo);
        *(u32*)(oh + o1 + nf * 8 + c2) = hi;
        *(u32*)(ol + o1 + nf * 8 + c2) = lo;
    }
}

// ---------------------------------------------------------------------------
extern "C" void kernel_launch(void* const* d_in, const int* in_sizes, int n_in,
                              void* d_out, int out_size) {
    const float* x   = (const float*)d_in[0];
    const float* g   = (const float*)d_in[1];
    const float* b   = (const float*)d_in[2];
    const float* caw = (const float*)d_in[3];
    const float* cab = (const float*)d_in[4];
    const float* cpw = (const float*)d_in[5];
    const float* cpb = (const float*)d_in[6];
    const float* tow = (const float*)d_in[7];
    float* out = (float*)d_out;

    bf16 *yh, *yl, *qh, *ql, *oh, *ol;
    bf16 *cawh, *cawl, *cpwh, *cpwl, *towh, *towl, *w2h, *w2l;
    float *b2, *wpart;
    cudaGetSymbolAddress((void**)&yh, g_yh);
    cudaGetSymbolAddress((void**)&yl, g_yl);
    cudaGetSymbolAddress((void**)&qh, g_qkvh);
    cudaGetSymbolAddress((void**)&ql, g_qkvl);
    cudaGetSymbolAddress((void**)&oh, g_oh);
    cudaGetSymbolAddress((void**)&ol, g_ol);
    cudaGetSymbolAddress((void**)&cawh, g_cawh);
    cudaGetSymbolAddress((void**)&cawl, g_cawl);
    cudaGetSymbolAddress((void**)&cpwh, g_cpwh);
    cudaGetSymbolAddress((void**)&cpwl, g_cpwl);
    cudaGetSymbolAddress((void**)&towh, g_towh);
    cudaGetSymbolAddress((void**)&towl, g_towl);
    cudaGetSymbolAddress((void**)&w2h, g_w2h);
    cudaGetSymbolAddress((void**)&w2l, g_w2l);
    cudaGetSymbolAddress((void**)&b2, g_b2);
    cudaGetSymbolAddress((void**)&wpart, g_wpart);

    cudaFuncSetAttribute(hgemm3_kernel<false, true, 2>,
        cudaFuncAttributeMaxDynamicSharedMemorySize, 108544);
    cudaFuncSetAttribute(hgemm3_kernel<false, true, 0>,
        cudaFuncAttributeMaxDynamicSharedMemorySize, 108544);
    cudaFuncSetAttribute(hgemm3_kernel<true, false, 3>,
        cudaFuncAttributeMaxDynamicSharedMemorySize, 122880);
    cudaFuncSetAttribute(attn_mma_kernel,
        cudaFuncAttributeMaxDynamicSharedMemorySize, ATT_SMEM);

    // Fork/join side stream (R14/R15 structure)
    cudaStream_t s2;
    cudaStreamCreateWithFlags(&s2, cudaStreamNonBlocking);
    cudaEvent_t eRoot, eSplit, eFold;
    cudaEventCreateWithFlags(&eRoot, cudaEventDisableTiming);
    cudaEventCreateWithFlags(&eSplit, cudaEventDisableTiming);
    cudaEventCreateWithFlags(&eFold, cudaEventDisableTiming);

    cudaEventRecord(eRoot, 0);
    cudaStreamWaitEvent(s2, eRoot, 0);

    // side stream: weight prep
    split_all_kernel<<<5120, 256, 0, s2>>>(caw, cawh, cawl, cpw, cpwh, cpwl,
                                           tow, towh, towl);
    cudaEventRecord(eSplit, s2);
    hgemm3_kernel<true, false, 3>
        <<<dim3(DIMM / 256, DIMM / 128, 8), 256, 122880, s2>>>(
        cpwh, cpwl, towh, towl, nullptr, wpart, nullptr, nullptr,
        DIMM, DIMM, DIMM);
    wreduce_kernel<<<DIMM * DIMM / 1024, 256, 0, s2>>>(wpart, w2h, w2l);
    bias_fold_kernel<<<DIMM / 8, 256, 0, s2>>>(cpb, tow, b2);
    cudaEventRecord(eFold, s2);

    // main stream: 1. LayerNorm (concurrent with weight prep)
    ln_kernel<<<MM, 256>>>(x, g, b, yh, yl);

    // join 1: qkv needs split weights
    cudaStreamWaitEvent(0, eSplit, 0);

    // 2. qkv GEMM with fused bias + per-head L2 norm + hi/lo split
    hgemm3_kernel<false, true, 2>
        <<<dim3(3 * DIMM / 256, MM / 128), 256, 108544>>>(
        yh, yl, cawh, cawl, cab, nullptr, qh, ql, MM, 3 * DIMM, DIMM);

    // 3. tensor-core causal attention (2 CTAs/SM) -> bf16 hi/lo
    attn_mma_kernel<<<dim3(NN / 128, BB * HH), 256, ATT_SMEM>>>(qh, ql, oh, ol);

    // join 2: final GEMM needs W2/b2
    cudaStreamWaitEvent(0, eFold, 0);

    // 4. out = o @ W2 + b2  (single fused projection, fp32 out)
    hgemm3_kernel<false, true, 0>
        <<<dim3(DIMM / 256, MM / 128), 256, 108544>>>(
        oh, ol, w2h, w2l, b2, out, nullptr, nullptr, MM, DIMM, DIMM);
}

// round 17
// speedup vs baseline: 1.0425x; 1.0425x over previous
#include <cuda_runtime.h>
#include <cuda_bf16.h>
#include <cstdint>
#include <math.h>

typedef unsigned int u32;
typedef __nv_bfloat16 bf16;

// Problem constants
#define BB   2
#define NN   2048
#define DIMM 1024
#define HH   16
#define DHH  64
#define MM   (BB*NN)          // 4096 tokens

// Scratch (allocation-free rule: __device__ globals)
__device__ bf16  g_yh [MM * DIMM];
__device__ bf16  g_yl [MM * DIMM];
__device__ bf16  g_qkvh[MM * 3 * DIMM];
__device__ bf16  g_qkvl[MM * 3 * DIMM];
__device__ bf16  g_oh [MM * DIMM];
__device__ bf16  g_ol [MM * DIMM];
__device__ bf16  g_cawh[DIMM * 3 * DIMM];
__device__ bf16  g_cawl[DIMM * 3 * DIMM];
__device__ bf16  g_cpwh[DIMM * DIMM];
__device__ bf16  g_cpwl[DIMM * DIMM];
__device__ bf16  g_towh[DIMM * DIMM];
__device__ bf16  g_towl[DIMM * DIMM];
__device__ bf16  g_w2h [DIMM * DIMM];     // W2 = cpw @ tow^T
__device__ bf16  g_w2l [DIMM * DIMM];
__device__ float g_b2  [DIMM];            // b2 = cpb @ tow^T
__device__ float g_wpart[8 * DIMM * DIMM];// split-K partials for W2

__device__ __forceinline__ float warp_sum(float v) {
#pragma unroll
    for (int o = 16; o; o >>= 1) v += __shfl_xor_sync(0xffffffffu, v, o);
    return v;
}

// ---------------------------------------------------------------------------
// MMA / ldmatrix / cp.async / split helpers
// ---------------------------------------------------------------------------
__device__ __forceinline__ void ldm4(u32* r, const bf16* p) {
    u32 a = (u32)__cvta_generic_to_shared(p);
    asm volatile("ldmatrix.sync.aligned.m8n8.x4.shared.b16 {%0,%1,%2,%3}, [%4];"
        : "=r"(r[0]), "=r"(r[1]), "=r"(r[2]), "=r"(r[3]) : "r"(a));
}
__device__ __forceinline__ void ldm4t(u32* r, const bf16* p) {
    u32 a = (u32)__cvta_generic_to_shared(p);
    asm volatile("ldmatrix.sync.aligned.m8n8.x4.trans.shared.b16 {%0,%1,%2,%3}, [%4];"
        : "=r"(r[0]), "=r"(r[1]), "=r"(r[2]), "=r"(r[3]) : "r"(a));
}
__device__ __forceinline__ void mma16816(float* c, const u32* a, const u32* b) {
    asm volatile("mma.sync.aligned.m16n8k16.row.col.f32.bf16.bf16.f32 "
        "{%0,%1,%2,%3}, {%4,%5,%6,%7}, {%8,%9}, {%0,%1,%2,%3};"
        : "+f"(c[0]), "+f"(c[1]), "+f"(c[2]), "+f"(c[3])
        : "r"(a[0]), "r"(a[1]), "r"(a[2]), "r"(a[3]), "r"(b[0]), "r"(b[1]));
}
__device__ __forceinline__ void cpa16(bf16* dst, const bf16* src) {
    u32 d = (u32)__cvta_generic_to_shared(dst);
    asm volatile("cp.async.cg.shared.global [%0], [%1], 16;" :: "r"(d), "l"(src));
}
__device__ __forceinline__ void cpa_commit() {
    asm volatile("cp.async.commit_group;");
}
__device__ __forceinline__ void cpa_wait0() {
    asm volatile("cp.async.wait_group 0;");
}
__device__ __forceinline__ void cpa_wait1() {
    asm volatile("cp.async.wait_group 1;");
}
__device__ __forceinline__ u32 p2(float a, float b) {
    __nv_bfloat162 t = __floats2bfloat162_rn(a, b);
    return *reinterpret_cast<u32*>(&t);
}
__device__ __forceinline__ void split2(float a, float b, u32& hi, u32& lo) {
    float ha = __bfloat162float(__float2bfloat16_rn(a));
    float hb = __bfloat162float(__float2bfloat16_rn(b));
    hi = p2(a, b);
    lo = p2(a - ha, b - hb);
}
__device__ __forceinline__ void split_store4(float4 v, bf16* ph, bf16* pl) {
    float hx = __bfloat162float(__float2bfloat16_rn(v.x));
    float hy = __bfloat162float(__float2bfloat16_rn(v.y));
    float hz = __bfloat162float(__float2bfloat16_rn(v.z));
    float hw = __bfloat162float(__float2bfloat16_rn(v.w));
    *reinterpret_cast<uint2*>(ph) = make_uint2(p2(hx, hy), p2(hz, hw));
    *reinterpret_cast<uint2*>(pl) =
        make_uint2(p2(v.x - hx, v.y - hy), p2(v.z - hz, v.w - hw));
}

// ---------------------------------------------------------------------------
// fp32 -> bf16 hi/lo split of all three weights in one launch
// ---------------------------------------------------------------------------
__global__ void __launch_bounds__(256) split_all_kernel(
        const float* __restrict__ caw, bf16* __restrict__ cawh, bf16* __restrict__ cawl,
        const float* __restrict__ cpw, bf16* __restrict__ cpwh, bf16* __restrict__ cpwl,
        const float* __restrict__ tow, bf16* __restrict__ towh, bf16* __restrict__ towl) {
    int bid = blockIdx.x;
    const float* in;
    bf16 *h, *l;
    int base;
    if (bid < 3072)      { in = caw; h = cawh; l = cawl; base = bid; }
    else if (bid < 4096) { in = cpw; h = cpwh; l = cpwl; base = bid - 3072; }
    else                 { in = tow; h = towh; l = towl; base = bid - 4096; }
    int i = (base * 256 + threadIdx.x) * 4;
    float4 v = *(const float4*)(in + i);
    split_store4(v, h + i, l + i);
}

// ---------------------------------------------------------------------------
// reduce 8 split-K partials -> bf16 hi/lo
// ---------------------------------------------------------------------------
__global__ void __launch_bounds__(256) wreduce_kernel(const float* __restrict__ part,
                                                      bf16* __restrict__ h,
                                                      bf16* __restrict__ l) {
    int i = (blockIdx.x * 256 + threadIdx.x) * 4;
    float4 s = *(const float4*)(part + i);
#pragma unroll
    for (int z = 1; z < 8; z++) {
        float4 v = *(const float4*)(part + (size_t)z * DIMM * DIMM + i);
        s.x += v.x; s.y += v.y; s.z += v.z; s.w += v.w;
    }
    split_store4(s, h + i, l + i);
}

// ---------------------------------------------------------------------------
// b2[j] = sum_k cpb[k] * tow[j,k]. One warp per output row.
// ---------------------------------------------------------------------------
__global__ void __launch_bounds__(256) bias_fold_kernel(
        const float* __restrict__ cpb, const float* __restrict__ tow,
        float* __restrict__ b2) {
    int j = blockIdx.x * 8 + (threadIdx.x >> 5);
    int lane = threadIdx.x & 31;
    const float* tr = tow + (size_t)j * DIMM;
    float s = 0.f;
#pragma unroll
    for (int k = lane * 4; k < DIMM; k += 128) {
        float4 t = *(const float4*)(tr + k);
        float4 c = *(const float4*)(cpb + k);
        s += t.x * c.x + t.y * c.y + t.z * c.z + t.w * c.w;
    }
    s = warp_sum(s);
    if (lane == 0) b2[j] = s;
}

// ---------------------------------------------------------------------------
// LayerNorm -> bf16 hi/lo
// ---------------------------------------------------------------------------
__global__ void __launch_bounds__(256) ln_kernel(const float* __restrict__ x,
                                                 const float* __restrict__ g,
                                                 const float* __restrict__ b,
                                                 bf16* __restrict__ yh,
                                                 bf16* __restrict__ yl) {
    int row = blockIdx.x;
    int t = threadIdx.x;
    const float* xr = x + (size_t)row * DIMM;
    float4 v = *(const float4*)(xr + t * 4);
    float s  = v.x + v.y + v.z + v.w;
    float ss = v.x*v.x + v.y*v.y + v.z*v.z + v.w*v.w;
    __shared__ float red[16];
    float s1 = warp_sum(s), s2 = warp_sum(ss);
    int w = t >> 5, lane = t & 31;
    if (lane == 0) { red[w] = s1; red[8 + w] = s2; }
    __syncthreads();
    float tot = 0.f, tot2 = 0.f;
#pragma unroll
    for (int i = 0; i < 8; i++) { tot += red[i]; tot2 += red[8 + i]; }
    float mu  = tot  * (1.f / DIMM);
    float var = tot2 * (1.f / DIMM) - mu * mu;
    float inv = rsqrtf(var + 1e-5f);
    float4 gv = *(const float4*)(g + t * 4);
    float4 bv = *(const float4*)(b + t * 4);
    float4 o;
    o.x = (v.x - mu) * inv * gv.x + bv.x;
    o.y = (v.y - mu) * inv * gv.y + bv.y;
    o.z = (v.z - mu) * inv * gv.z + bv.z;
    o.w = (v.w - mu) * inv * gv.w + bv.w;
    size_t off = (size_t)row * DIMM + t * 4;
    split_store4(o, yh + off, yl + off);
}

// ---------------------------------------------------------------------------
// bf16x3 tensor-core GEMM, 128x256 tile, BK=32, 2-stage cp.async. (R11)
// OMODE: 0 fp32 out, 1 bf16 hi/lo out, 2 qkv fused (bias+L2 norm+split),
//        3 split-K partial fp32 out
// ---------------------------------------------------------------------------
#define SA3 40
#define SB3 264

template <bool TRANSB, bool HASBIAS, int OMODE>
__global__ void __launch_bounds__(256) hgemm3_kernel(
        const bf16* __restrict__ Ahg, const bf16* __restrict__ Alg,
        const bf16* __restrict__ Bhg, const bf16* __restrict__ Blg,
        const float* __restrict__ bias,
        float* __restrict__ C, bf16* __restrict__ Ch, bf16* __restrict__ Cl,
        int M, int N, int K) {
    extern __shared__ __align__(16) bf16 smem[];
    constexpr int A_E = 128 * SA3;
    constexpr int B_E = TRANSB ? 256 * SA3 : 32 * SB3;
    constexpr int STAGE_E = 2 * A_E + 2 * B_E;

    int tid = threadIdx.x;
    int bm = blockIdx.y * 128, bn = blockIdx.x * 256;
    int wid = tid >> 5, lane = tid & 31;
    int wm = (wid & 3) * 32, wn = (wid >> 2) * 128;
    int grp = lane >> 3, lr = lane & 7;

    if (OMODE == 3) C += (size_t)blockIdx.z * M * N;

    auto load_stage = [&](int s, int k0) {
        bf16* sAh = smem + s * STAGE_E;
        bf16* sAl = sAh + A_E;
        bf16* sBh = sAl + A_E;
        bf16* sBl = sBh + B_E;
#pragma unroll
        for (int i = 0; i < 2; i++) {
            int c = tid + i * 256;
            int row = c >> 2, kg = (c & 3) * 8;
            size_t src = (size_t)(bm + row) * K + k0 + kg;
            cpa16(&sAh[row * SA3 + kg], Ahg + src);
            cpa16(&sAl[row * SA3 + kg], Alg + src);
        }
        if (!TRANSB) {
#pragma unroll
            for (int i = 0; i < 4; i++) {
                int c = tid + i * 256;
                int row = c >> 5, col = (c & 31) * 8;
                size_t src = (size_t)(k0 + row) * N + bn + col;
                cpa16(&sBh[row * SB3 + col], Bhg + src);
                cpa16(&sBl[row * SB3 + col], Blg + src);
            }
        } else {
#pragma unroll
            for (int i = 0; i < 4; i++) {
                int c = tid + i * 256;
                int row = c >> 2, kg = (c & 3) * 8;
                size_t src = (size_t)(bn + row) * K + k0 + kg;
                cpa16(&sBh[row * SA3 + kg], Bhg + src);
                cpa16(&sBl[row * SA3 + kg], Blg + src);
            }
        }
    };

    float acc[2][16][4];
#pragma unroll
    for (int i = 0; i < 2; i++)
#pragma unroll
        for (int j = 0; j < 16; j++)
#pragma unroll
            for (int q = 0; q < 4; q++) acc[i][j][q] = 0.f;

    int arow0 = wm + ((grp & 1) << 3) + lr;

    int NK_total = K / 32;
    int it0 = 0, it1 = NK_total;
    if (OMODE == 3) {
        int per = NK_total / gridDim.z;
        it0 = blockIdx.z * per;
        it1 = it0 + per;
    }

    load_stage(0, it0 * 32);
    cpa_commit();

    int stage = 0;
    for (int it = it0; it < it1; it++) {
        cpa_wait0();
        __syncthreads();
        if (it + 1 < it1) { load_stage(stage ^ 1, (it + 1) * 32); cpa_commit(); }

        bf16* sAh = smem + stage * STAGE_E;
        bf16* sAl = sAh + A_E;
        bf16* sBh = sAl + A_E;
        bf16* sBl = sBh + B_E;

#pragma unroll
        for (int ks = 0; ks < 2; ks++) {
            int acol = ks * 16 + ((grp & 2) ? 8 : 0);
            u32 ah[2][4], al[2][4];
            ldm4(ah[0], &sAh[arow0 * SA3 + acol]);
            ldm4(ah[1], &sAh[(arow0 + 16) * SA3 + acol]);
            ldm4(al[0], &sAl[arow0 * SA3 + acol]);
            ldm4(al[1], &sAl[(arow0 + 16) * SA3 + acol]);

#pragma unroll
            for (int nb = 0; nb < 8; nb++) {
                u32 rh[4], rl[4];
                if (!TRANSB) {
                    int krow = ks * 16 + ((grp & 1) << 3) + lr;
                    int ncol = wn + nb * 16 + ((grp & 2) ? 8 : 0);
                    ldm4t(rh, &sBh[krow * SB3 + ncol]);
                    ldm4t(rl, &sBl[krow * SB3 + ncol]);
                } else {
                    int nrow = wn + nb * 16 + ((grp & 2) ? 8 : 0) + lr;
                    int kcol = ks * 16 + ((grp & 1) ? 8 : 0);
                    ldm4(rh, &sBh[nrow * SA3 + kcol]);
                    ldm4(rl, &sBl[nrow * SA3 + kcol]);
                }
                int nf0 = 2 * nb, nf1 = 2 * nb + 1;
#pragma unroll
                for (int mi = 0; mi < 2; mi++) {
                    mma16816(acc[mi][nf0], ah[mi], rh);
                    mma16816(acc[mi][nf0], al[mi], rh);
                    mma16816(acc[mi][nf0], ah[mi], rl);
                    mma16816(acc[mi][nf1], ah[mi], rh + 2);
                    mma16816(acc[mi][nf1], al[mi], rh + 2);
                    mma16816(acc[mi][nf1], ah[mi], rl + 2);
                }
            }
        }
        __syncthreads();
        stage ^= 1;
    }

    int r = lane >> 2, c2v = (lane & 3) * 2;

    if (OMODE == 2) {
        bool donorm = (bn < 2 * DIMM);
#pragma unroll
        for (int nf = 0; nf < 16; nf++) {
            int col = bn + wn + nf * 8 + c2v;
            float b0 = bias[col], b1 = bias[col + 1];
#pragma unroll
            for (int mi = 0; mi < 2; mi++) {
                acc[mi][nf][0] += b0; acc[mi][nf][1] += b1;
                acc[mi][nf][2] += b0; acc[mi][nf][3] += b1;
            }
        }
#pragma unroll
        for (int gh = 0; gh < 2; gh++) {
            float ss[2][2] = {{0.f, 0.f}, {0.f, 0.f}};
#pragma unroll
            for (int nf = gh * 8; nf < gh * 8 + 8; nf++)
#pragma unroll
                for (int mi = 0; mi < 2; mi++) {
                    ss[mi][0] += acc[mi][nf][0] * acc[mi][nf][0]
                               + acc[mi][nf][1] * acc[mi][nf][1];
                    ss[mi][1] += acc[mi][nf][2] * acc[mi][nf][2]
                               + acc[mi][nf][3] * acc[mi][nf][3];
                }
            float inv[2][2];
#pragma unroll
            for (int mi = 0; mi < 2; mi++)
#pragma unroll
                for (int hf = 0; hf < 2; hf++) {
                    float v = ss[mi][hf];
                    v += __shfl_xor_sync(0xffffffffu, v, 1);
                    v += __shfl_xor_sync(0xffffffffu, v, 2);
                    inv[mi][hf] = donorm ? 1.f / fmaxf(sqrtf(v), 1e-12f) : 1.f;
                }
#pragma unroll
            for (int nf = gh * 8; nf < gh * 8 + 8; nf++) {
                int col = bn + wn + nf * 8 + c2v;
#pragma unroll
                for (int mi = 0; mi < 2; mi++) {
                    int row0 = bm + wm + mi * 16 + r;
                    size_t o0 = (size_t)row0 * N + col;
                    size_t o1 = (size_t)(row0 + 8) * N + col;
                    u32 hi, lo;
                    split2(acc[mi][nf][0] * inv[mi][0],
                           acc[mi][nf][1] * inv[mi][0], hi, lo);
                    *(u32*)(Ch + o0) = hi; *(u32*)(Cl + o0) = lo;
                    split2(acc[mi][nf][2] * inv[mi][1],
                           acc[mi][nf][3] * inv[mi][1], hi, lo);
                    *(u32*)(Ch + o1) = hi; *(u32*)(Cl + o1) = lo;
                }
            }
        }
        return;
    }

#pragma unroll
    for (int nf = 0; nf < 16; nf++) {
        int col = bn + wn + nf * 8 + c2v;
        float b0v = 0.f, b1v = 0.f;
        if (HASBIAS) { b0v = bias[col]; b1v = bias[col + 1]; }
#pragma unroll
        for (int mi = 0; mi < 2; mi++) {
            int row0 = bm + wm + mi * 16 + r;
            float v00 = acc[mi][nf][0] + b0v, v01 = acc[mi][nf][1] + b1v;
            float v10 = acc[mi][nf][2] + b0v, v11 = acc[mi][nf][3] + b1v;
            size_t o0 = (size_t)row0 * N + col;
            size_t o1 = (size_t)(row0 + 8) * N + col;
            if (OMODE == 1) {
                u32 hi, lo;
                split2(v00, v01, hi, lo);
                *(u32*)(Ch + o0) = hi; *(u32*)(Cl + o0) = lo;
                split2(v10, v11, hi, lo);
                *(u32*)(Ch + o1) = hi; *(u32*)(Cl + o1) = lo;
            } else {
                *(float2*)(C + o0) = make_float2(v00, v01);
                *(float2*)(C + o1) = make_float2(v10, v11);
            }
        }
    }
}

// ---------------------------------------------------------------------------
// Tensor-core causal flash-attention, FIXED-MAX softmax.
// Scores = 8 * (qn . kn) are bounded in [-8, 8] (L2-normalized q,k), so
// softmax uses constant max m = 8: no running max, no accumulator rescale,
// per-thread row-sum reduced once after the loop. Math identical to
// reference softmax (shift invariance).
// ---------------------------------------------------------------------------
#define KST 72
#define TILE_E (64 * KST)
#define ATT_SMEM (2 * 4 * TILE_E * 2)

__global__ void __launch_bounds__(256) attn_mma_kernel(
        const bf16* __restrict__ qkvh,
        const bf16* __restrict__ qkvl,
        bf16* __restrict__ oh, bf16* __restrict__ ol) {
    extern __shared__ __align__(16) bf16 asmem[];

    int bh_ = blockIdx.y;
    int b = bh_ >> 4, h = bh_ & 15;
    int q0 = (gridDim.x - 1 - blockIdx.x) * 128;
    int tid = threadIdx.x, wid = tid >> 5, lane = tid & 31;
    int grp = lane >> 3, lr = lane & 7;
    int wm = wid * 16;

    const size_t rs = 3 * DIMM;
    const bf16* qh_base = qkvh + (size_t)b * NN * rs + h * DHH;
    const bf16* ql_base = qkvl + (size_t)b * NN * rs + h * DHH;
    const bf16* kh_base = qh_base + DIMM;
    const bf16* kl_base = ql_base + DIMM;
    const bf16* vh_base = qh_base + 2 * DIMM;
    const bf16* vl_base = ql_base + 2 * DIMM;

    auto load_kv = [&](int s, int j0) {
        bf16* kh = asmem + s * 4 * TILE_E;
        bf16* kl = kh + TILE_E;
        bf16* vh = kh + 2 * TILE_E;
        bf16* vl = kh + 3 * TILE_E;
#pragma unroll
        for (int i = 0; i < 2; i++) {
            int c = tid + i * 256;
            int r = c >> 3, cc = (c & 7) * 8;
            size_t off = (size_t)(j0 + r) * rs + cc;
            cpa16(&kh[r * KST + cc], kh_base + off);
            cpa16(&kl[r * KST + cc], kl_base + off);
            cpa16(&vh[r * KST + cc], vh_base + off);
            cpa16(&vl[r * KST + cc], vl_base + off);
        }
    };

    load_kv(0, 0);
    cpa_commit();

    {
        bf16* q_h0 = asmem + 4 * TILE_E;
        bf16* q_l0 = q_h0 + TILE_E;
        bf16* q_h1 = q_h0 + 2 * TILE_E;
        bf16* q_l1 = q_h0 + 3 * TILE_E;
        for (int i = tid; i < 128 * 8; i += 256) {
            int r = i >> 3, c = (i & 7) * 8;
            size_t off = (size_t)(q0 + r) * rs + c;
            bf16* dh = (r < 64) ? &q_h0[r * KST + c] : &q_h1[(r - 64) * KST + c];
            bf16* dl = (r < 64) ? &q_l0[r * KST + c] : &q_l1[(r - 64) * KST + c];
            *(uint4*)dh = *(const uint4*)(qh_base + off);
            *(uint4*)dl = *(const uint4*)(ql_base + off);
        }
    }
    __syncthreads();
    u32 aq_h[4][4], aq_l[4][4];
    {
        bf16* q_h0 = asmem + 4 * TILE_E;
        const bf16* bh_p = (wm < 64) ? q_h0 : q_h0 + 2 * TILE_E;
        const bf16* bl_p = (wm < 64) ? q_h0 + TILE_E : q_h0 + 3 * TILE_E;
        int arow = (wm & 63) + ((grp & 1) << 3) + lr;
#pragma unroll
        for (int ks = 0; ks < 4; ks++) {
            int acol = ks * 16 + ((grp & 2) ? 8 : 0);
            ldm4(aq_h[ks], &bh_p[arow * KST + acol]);
            ldm4(aq_l[ks], &bl_p[arow * KST + acol]);
        }
    }
    __syncthreads();

    float l0 = 0.f, l1 = 0.f;     // per-thread row-sum partials
    float acc[8][4];
#pragma unroll
    for (int i = 0; i < 8; i++)
#pragma unroll
        for (int j = 0; j < 4; j++) acc[i][j] = 0.f;

    int c2 = (lane & 3) * 2;
    int qrow0 = q0 + wm + (lane >> 2);
    int qrow1 = qrow0 + 8;
    int ntiles = q0 / 64 + 2;

    for (int t = 0; t < ntiles; t++) {
        int s = t & 1;
        int j0 = t * 64;
        if (t + 1 < ntiles) {
            load_kv(s ^ 1, (t + 1) * 64);
            cpa_commit();
            cpa_wait1();
        } else {
            cpa_wait0();
        }
        __syncthreads();

        bf16* skh = asmem + s * 4 * TILE_E;
        bf16* skl = skh + TILE_E;
        bf16* svh = skh + 2 * TILE_E;
        bf16* svl = skh + 3 * TILE_E;

        float sv[8][4];
#pragma unroll
        for (int i = 0; i < 8; i++)
#pragma unroll
            for (int j = 0; j < 4; j++) sv[i][j] = 0.f;

#pragma unroll
        for (int ks = 0; ks < 4; ks++) {
            int kcol = ks * 16 + ((grp & 1) ? 8 : 0);
            u32 kh[4][4], kl[4][4];
#pragma unroll
            for (int nb = 0; nb < 4; nb++) {
                int nrow = nb * 16 + ((grp & 2) ? 8 : 0) + lr;
                ldm4(kh[nb], &skh[nrow * KST + kcol]);
                ldm4(kl[nb], &skl[nrow * KST + kcol]);
            }
            // term-major: 8 distinct accumulators between same-acc MMAs
#pragma unroll
            for (int nb = 0; nb < 4; nb++) {
                mma16816(sv[2 * nb],     aq_h[ks], &kh[nb][0]);
                mma16816(sv[2 * nb + 1], aq_h[ks], &kh[nb][2]);
            }
#pragma unroll
            for (int nb = 0; nb < 4; nb++) {
                mma16816(sv[2 * nb],     aq_l[ks], &kh[nb][0]);
                mma16816(sv[2 * nb + 1], aq_l[ks], &kh[nb][2]);
            }
#pragma unroll
            for (int nb = 0; nb < 4; nb++) {
                mma16816(sv[2 * nb],     aq_h[ks], &kl[nb][0]);
                mma16816(sv[2 * nb + 1], aq_h[ks], &kl[nb][2]);
            }
        }

        // fixed-max softmax: p = exp(8*s - 8), masked -> 0
        u32 ph[4][4], pl[4][4];
#pragma unroll
        for (int nf = 0; nf < 8; nf++) {
            int key = j0 + nf * 8 + c2;
#pragma unroll
            for (int c = 0; c < 2; c++) {
                float v0 = fmaf(sv[nf][c],     8.0f, -8.0f);
                float v1 = fmaf(sv[nf][2 + c], 8.0f, -8.0f);
                if (key + c > qrow0) v0 = -1e30f;
                if (key + c > qrow1) v1 = -1e30f;
                sv[nf][c] = v0; sv[nf][2 + c] = v1;
            }
        }
#pragma unroll
        for (int j = 0; j < 4; j++) {
            float e0 = __expf(sv[2 * j][0]);
            float e1 = __expf(sv[2 * j][1]);
            float e2 = __expf(sv[2 * j][2]);
            float e3 = __expf(sv[2 * j][3]);
            float e4 = __expf(sv[2 * j + 1][0]);
            float e5 = __expf(sv[2 * j + 1][1]);
            float e6 = __expf(sv[2 * j + 1][2]);
            float e7 = __expf(sv[2 * j + 1][3]);
            l0 += e0 + e1 + e4 + e5;
            l1 += e2 + e3 + e6 + e7;
            split2(e0, e1, ph[j][0], pl[j][0]);
            split2(e2, e3, ph[j][1], pl[j][1]);
            split2(e4, e5, ph[j][2], pl[j][2]);
            split2(e6, e7, ph[j][3], pl[j][3]);
        }

#pragma unroll
        for (int ks = 0; ks < 4; ks++) {
            int krow = ks * 16 + ((grp & 1) ? 8 : 0) + lr;
            u32 vh[4][4], vl[4][4];
#pragma unroll
            for (int nb = 0; nb < 4; nb++) {
                int ncol = nb * 16 + ((grp & 2) ? 8 : 0);
                ldm4t(vh[nb], &svh[krow * KST + ncol]);
                ldm4t(vl[nb], &svl[krow * KST + ncol]);
            }
            // term-major reorder (see S loop)
#pragma unroll
            for (int nb = 0; nb < 4; nb++) {
                mma16816(acc[2 * nb],     ph[ks], &vh[nb][0]);
                mma16816(acc[2 * nb + 1], ph[ks], &vh[nb][2]);
            }
#pragma unroll
            for (int nb = 0; nb < 4; nb++) {
                mma16816(acc[2 * nb],     pl[ks], &vh[nb][0]);
                mma16816(acc[2 * nb + 1], pl[ks], &vh[nb][2]);
            }
#pragma unroll
            for (int nb = 0; nb < 4; nb++) {
                mma16816(acc[2 * nb],     ph[ks], &vl[nb][0]);
                mma16816(acc[2 * nb + 1], ph[ks], &vl[nb][2]);
            }
        }
        __syncthreads();
    }

    // one-time row-sum reduction across the thread quad
    l0 += __shfl_xor_sync(0xffffffffu, l0, 1);
    l0 += __shfl_xor_sync(0xffffffffu, l0, 2);
    l1 += __shfl_xor_sync(0xffffffffu, l1, 1);
    l1 += __shfl_xor_sync(0xffffffffu, l1, 2);

    float inv0 = 1.f / l0, inv1 = 1.f / l1;
    size_t o0 = ((size_t)(b * NN) + qrow0) * DIMM + h * DHH;
    size_t o1 = o0 + (size_t)8 * DIMM;
#pragma unroll
    for (int nf = 0; nf < 8; nf++) {
        u32 hi, lo;
        split2(acc[nf][0] * inv0, acc[nf][1] * inv0, hi, lo);
        *(u32*)(oh + o0 + nf * 8 + c2) = hi;
        *(u32*)(ol + o0 + nf * 8 + c2) = lo;
        split2(acc[nf][2] * inv1, acc[nf][3] * inv1, hi, lo);
        *(u32*)(oh + o1 + nf * 8 + c2) = hi;
        *(u32*)(ol + o1 + nf * 8 + c2) = lo;
    }
}

// ---------------------------------------------------------------------------
extern "C" void kernel_launch(void* const* d_in, const int* in_sizes, int n_in,
                              void* d_out, int out_size) {
    const float* x   = (const float*)d_in[0];
    const float* g   = (const float*)d_in[1];
    const float* b   = (const float*)d_in[2];
    const float* caw = (const float*)d_in[3];
    const float* cab = (const float*)d_in[4];
    const float* cpw = (const float*)d_in[5];
    const float* cpb = (const float*)d_in[6];
    const float* tow = (const float*)d_in[7];
    float* out = (float*)d_out;

    bf16 *yh, *yl, *qh, *ql, *oh, *ol;
    bf16 *cawh, *cawl, *cpwh, *cpwl, *towh, *towl, *w2h, *w2l;
    float *b2, *wpart;
    cudaGetSymbolAddress((void**)&yh, g_yh);
    cudaGetSymbolAddress((void**)&yl, g_yl);
    cudaGetSymbolAddress((void**)&qh, g_qkvh);
    cudaGetSymbolAddress((void**)&ql, g_qkvl);
    cudaGetSymbolAddress((void**)&oh, g_oh);
    cudaGetSymbolAddress((void**)&ol, g_ol);
    cudaGetSymbolAddress((void**)&cawh, g_cawh);
    cudaGetSymbolAddress((void**)&cawl, g_cawl);
    cudaGetSymbolAddress((void**)&cpwh, g_cpwh);
    cudaGetSymbolAddress((void**)&cpwl, g_cpwl);
    cudaGetSymbolAddress((void**)&towh, g_towh);
    cudaGetSymbolAddress((void**)&towl, g_towl);
    cudaGetSymbolAddress((void**)&w2h, g_w2h);
    cudaGetSymbolAddress((void**)&w2l, g_w2l);
    cudaGetSymbolAddress((void**)&b2, g_b2);
    cudaGetSymbolAddress((void**)&wpart, g_wpart);

    cudaFuncSetAttribute(hgemm3_kernel<false, true, 2>,
        cudaFuncAttributeMaxDynamicSharedMemorySize, 108544);
    cudaFuncSetAttribute(hgemm3_kernel<false, true, 0>,
        cudaFuncAttributeMaxDynamicSharedMemorySize, 108544);
    cudaFuncSetAttribute(hgemm3_kernel<true, false, 3>,
        cudaFuncAttributeMaxDynamicSharedMemorySize, 122880);
    cudaFuncSetAttribute(attn_mma_kernel,
        cudaFuncAttributeMaxDynamicSharedMemorySize, ATT_SMEM);

    // Fork/join side stream (R14/R15 structure)
    cudaStream_t s2;
    cudaStreamCreateWithFlags(&s2, cudaStreamNonBlocking);
    cudaEvent_t eRoot, eSplit, eFold;
    cudaEventCreateWithFlags(&eRoot, cudaEventDisableTiming);
    cudaEventCreateWithFlags(&eSplit, cudaEventDisableTiming);
    cudaEventCreateWithFlags(&eFold, cudaEventDisableTiming);

    cudaEventRecord(eRoot, 0);
    cudaStreamWaitEvent(s2, eRoot, 0);

    // side stream: weight prep
    split_all_kernel<<<5120, 256, 0, s2>>>(caw, cawh, cawl, cpw, cpwh, cpwl,
                                           tow, towh, towl);
    cudaEventRecord(eSplit, s2);
    hgemm3_kernel<true, false, 3>
        <<<dim3(DIMM / 256, DIMM / 128, 8), 256, 122880, s2>>>(
        cpwh, cpwl, towh, towl, nullptr, wpart, nullptr, nullptr,
        DIMM, DIMM, DIMM);
    wreduce_kernel<<<DIMM * DIMM / 1024, 256, 0, s2>>>(wpart, w2h, w2l);
    bias_fold_kernel<<<DIMM / 8, 256, 0, s2>>>(cpb, tow, b2);
    cudaEventRecord(eFold, s2);

    // main stream: 1. LayerNorm (concurrent with weight prep)
    ln_kernel<<<MM, 256>>>(x, g, b, yh, yl);

    // join 1: qkv needs split weights
    cudaStreamWaitEvent(0, eSplit, 0);

    // 2. qkv GEMM with fused bias + per-head L2 norm + hi/lo split
    hgemm3_kernel<false, true, 2>
        <<<dim3(3 * DIMM / 256, MM / 128), 256, 108544>>>(
        yh, yl, cawh, cawl, cab, nullptr, qh, ql, MM, 3 * DIMM, DIMM);

    // 3. tensor-core causal attention (fixed-max softmax) -> bf16 hi/lo
    attn_mma_kernel<<<dim3(NN / 128, BB * HH), 256, ATT_SMEM>>>(qh, ql, oh, ol);

    // join 2: final GEMM needs W2/b2
    cudaStreamWaitEvent(0, eFold, 0);

    // 4. out = o @ W2 + b2  (single fused projection, fp32 out)
    hgemm3_kernel<false, true, 0>
        <<<dim3(DIMM / 256, MM / 128), 256, 108544>>>(
        oh, ol, w2h, w2l, b2, out, nullptr, nullptr, MM, DIMM, DIMM);
}